// round 12
// baseline (speedup 1.0000x reference)
#include <cuda_runtime.h>

// SDF_75806172774865 — R4 kernel shape (full grid, 92% occ, regs=32,
// DRAM 72.3%) + in-kernel ticket finalization (saves the init launch).
// points: (N,P,3) f32; v,vn: (N,P,K,3) f32; sr: (N,P,K) f32; out: (N,) f32
//
// Warp handles points {2w, 2w+1}; lanes stride over k; 14 loads per
// warp-iteration; __fdividef. Block results go to device scratch via 2
// atomics; the last block (ticket) writes out and resets scratch/ticket so
// graph replays stay deterministic.

#define WPB 16
#define TPB (WPB * 32)

__device__ float        g_scratch[2];  // zero-init at module load
__device__ unsigned int g_ticket;      // zero-init at module load

__global__ void sdf_init_out(float* out, int n) {   // fallback path only
    int i = threadIdx.x;
    if (i < n) out[i] = 0.0f;
}

__global__ __launch_bounds__(TPB)
void sdf_fused60(const float* __restrict__ points,
                 const float* __restrict__ v,
                 const float* __restrict__ vn,
                 const float* __restrict__ sr,
                 float* __restrict__ out,
                 int total_pts,   // N*P (even)
                 int P,
                 int nblocks)
{
    constexpr int K = 60;
    __shared__ float s_acc[2];
    const int tid  = threadIdx.x;
    if (tid < 2) s_acc[tid] = 0.0f;
    __syncthreads();

    const int warp = tid >> 5;
    const int lane = tid & 31;
    const int ptA  = (blockIdx.x * WPB + warp) * 2;
    const int ptB  = ptA + 1;

    if (ptA < total_pts) {
        const float* ppA = points + (size_t)ptA * 3;
        const float pxA = ppA[0], pyA = ppA[1], pzA = ppA[2];
        const float* vA  = v  + (size_t)ptA * (K * 3);
        const float* vnA = vn + (size_t)ptA * (K * 3);
        const float* srA = sr + (size_t)ptA * K;
        const float* ppB = points + (size_t)ptB * 3;
        const float pxB = ppB[0], pyB = ppB[1], pzB = ppB[2];
        const float* vB  = v  + (size_t)ptB * (K * 3);
        const float* vnB = vn + (size_t)ptB * (K * 3);
        const float* srB = sr + (size_t)ptB * K;

        float numA = 0.0f, denA = 0.0f;
        float numB = 0.0f, denB = 0.0f;

        #pragma unroll
        for (int k = lane; k < K; k += 32) {
            const int b = k * 3;
            // 14 loads issued up front
            const float avx = vA[b + 0],  avy = vA[b + 1],  avz = vA[b + 2];
            const float anx = vnA[b + 0], any_ = vnA[b + 1], anz = vnA[b + 2];
            const float ra  = srA[k];
            const float bvx = vB[b + 0],  bvy = vB[b + 1],  bvz = vB[b + 2];
            const float bnx = vnB[b + 0], bny = vnB[b + 1], bnz = vnB[b + 2];
            const float rb  = srB[k];

            {
                const float dx = pxA - avx, dy = pyA - avy, dz = pzA - avz;
                const float d  = dx * dx + dy * dy + dz * dz;
                const float w  = 1.0f - __fdividef(d, ra);
                const float w2 = w * w;
                const float phi = (d < ra) ? (w2 * w2) : 1e-18f;
                const float dot = anx * dx + any_ * dy + anz * dz;
                numA = fmaf(phi, dot, numA);
                denA += phi;
            }
            {
                const float dx = pxB - bvx, dy = pyB - bvy, dz = pzB - bvz;
                const float d  = dx * dx + dy * dy + dz * dz;
                const float w  = 1.0f - __fdividef(d, rb);
                const float w2 = w * w;
                const float phi = (d < rb) ? (w2 * w2) : 1e-18f;
                const float dot = bnx * dx + bny * dy + bnz * dz;
                numB = fmaf(phi, dot, numB);
                denB += phi;
            }
        }

        #pragma unroll
        for (int off = 16; off > 0; off >>= 1) {
            numA += __shfl_xor_sync(0xffffffffu, numA, off);
            denA += __shfl_xor_sync(0xffffffffu, denA, off);
            numB += __shfl_xor_sync(0xffffffffu, numB, off);
            denB += __shfl_xor_sync(0xffffffffu, denB, off);
        }

        if (lane == 0) {
            const float sdfA = __fdividef(numA, denA);
            const float sdfB = __fdividef(numB, denB);
            float acc = sdfA * sdfA;
            if ((ptB / P) == (ptA / P)) {
                acc += sdfB * sdfB;
                atomicAdd(&s_acc[ptA / P], acc);
            } else {
                atomicAdd(&s_acc[ptA / P], acc);
                atomicAdd(&s_acc[ptB / P], sdfB * sdfB);
            }
        }
    }

    __syncthreads();

    // ---- finalize: scratch accumulation + ticket; last block writes out ----
    if (tid == 0) {
        const float v0 = s_acc[0];
        const float v1 = s_acc[1];
        if (v0 != 0.0f) atomicAdd(&g_scratch[0], v0);
        if (v1 != 0.0f) atomicAdd(&g_scratch[1], v1);
        __threadfence();
        const unsigned t = atomicAdd(&g_ticket, 1u);
        if (t == (unsigned)(nblocks - 1)) {
            __threadfence();
            out[0] = atomicExch(&g_scratch[0], 0.0f);
            out[1] = atomicExch(&g_scratch[1], 0.0f);
            atomicExch(&g_ticket, 0u);   // reset for next graph replay
        }
    }
}

// ---- generic fallback (any K / N / shape) ----
#define FB_WARPS 16
__global__ __launch_bounds__(FB_WARPS * 32)
void sdf_kernel_generic(const float* __restrict__ points,
                        const float* __restrict__ v,
                        const float* __restrict__ vn,
                        const float* __restrict__ sr,
                        float* __restrict__ out,
                        int total_pts, int P, int K)
{
    __shared__ float s_acc[2];
    const int tid  = threadIdx.x;
    if (tid < 2) s_acc[tid] = 0.0f;
    __syncthreads();

    const int warp = tid >> 5;
    const int lane = tid & 31;
    const int pt   = blockIdx.x * FB_WARPS + warp;

    if (pt < total_pts) {
        const float* pp = points + (size_t)pt * 3;
        const float px = pp[0], py = pp[1], pz = pp[2];
        const float* vb  = v  + (size_t)pt * K * 3;
        const float* vnb = vn + (size_t)pt * K * 3;
        const float* srb = sr + (size_t)pt * K;

        float num = 0.0f, den = 0.0f;
        for (int k = lane; k < K; k += 32) {
            const int b = k * 3;
            const float dx = px - vb[b + 0];
            const float dy = py - vb[b + 1];
            const float dz = pz - vb[b + 2];
            const float d  = dx * dx + dy * dy + dz * dz;
            const float r  = srb[k];
            const float w  = 1.0f - d / r;
            const float w2 = w * w;
            const float phi = (d < r) ? (w2 * w2) : 1e-18f;
            const float dot = vnb[b + 0] * dx + vnb[b + 1] * dy + vnb[b + 2] * dz;
            num = fmaf(phi, dot, num);
            den += phi;
        }
        #pragma unroll
        for (int off = 16; off > 0; off >>= 1) {
            num += __shfl_xor_sync(0xffffffffu, num, off);
            den += __shfl_xor_sync(0xffffffffu, den, off);
        }
        if (lane == 0) {
            const float sdf = num / den;
            atomicAdd(&s_acc[pt / P], sdf * sdf);
        }
    }
    __syncthreads();
    if (tid < 2) {
        const float val = s_acc[tid];
        if (val != 0.0f) atomicAdd(&out[tid], val);
    }
}

extern "C" void kernel_launch(void* const* d_in, const int* in_sizes, int n_in,
                              void* d_out, int out_size)
{
    const float* points = (const float*)d_in[0];
    const float* v      = (const float*)d_in[1];
    const float* vn     = (const float*)d_in[2];
    const float* sr     = (const float*)d_in[3];
    float* out          = (float*)d_out;

    const int total_pts = in_sizes[0] / 3;          // N*P
    const int N         = out_size;                 // 2
    const int P         = total_pts / N;            // 100000
    const int K         = in_sizes[3] / total_pts;  // 60

    if (K == 60 && N == 2 && (total_pts % 2) == 0) {
        const int pairs  = total_pts / 2;
        const int blocks = (pairs + WPB - 1) / WPB;
        sdf_fused60<<<blocks, TPB>>>(points, v, vn, sr, out,
                                     total_pts, P, blocks);
    } else {
        sdf_init_out<<<1, 32>>>(out, N);
        const int blocks = (total_pts + FB_WARPS - 1) / FB_WARPS;
        sdf_kernel_generic<<<blocks, FB_WARPS * 32>>>(points, v, vn, sr, out,
                                                      total_pts, P, K);
    }
}

// round 16
// speedup vs baseline: 1.0050x; 1.0050x over previous
#include <cuda_runtime.h>

// SDF_75806172774865 — R4 body (full grid, regs=32, DRAM 72.3%) + fused
// ticket finalize WITHOUT __threadfence (which emits CCTL.IVALL = per-block
// L1D flush, measured -4us in R12). Ordering is carried by an acq_rel
// atomic on the ticket itself; all scratch accesses are atomics (L1-bypass,
// L2-coherent), so no generic fence is required.
// points: (N,P,3) f32; v,vn: (N,P,K,3) f32; sr: (N,P,K) f32; out: (N,) f32

#define WPB 16
#define TPB (WPB * 32)

__device__ float        g_scratch[2];  // zero-init at module load
__device__ unsigned int g_ticket;      // zero-init at module load

__device__ __forceinline__ unsigned ticket_inc_acq_rel() {
    unsigned t;
    asm volatile("atom.acq_rel.gpu.add.u32 %0, [%1], 1;"
                 : "=r"(t) : "l"(&g_ticket) : "memory");
    return t;
}

__global__ void sdf_init_out(float* out, int n) {   // fallback path only
    int i = threadIdx.x;
    if (i < n) out[i] = 0.0f;
}

__global__ __launch_bounds__(TPB)
void sdf_fused60(const float* __restrict__ points,
                 const float* __restrict__ v,
                 const float* __restrict__ vn,
                 const float* __restrict__ sr,
                 float* __restrict__ out,
                 int total_pts,   // N*P (even)
                 int P,
                 int nblocks)
{
    constexpr int K = 60;
    __shared__ float s_acc[2];
    const int tid  = threadIdx.x;
    if (tid < 2) s_acc[tid] = 0.0f;
    __syncthreads();

    const int warp = tid >> 5;
    const int lane = tid & 31;
    const int ptA  = (blockIdx.x * WPB + warp) * 2;
    const int ptB  = ptA + 1;

    if (ptA < total_pts) {
        const float* ppA = points + (size_t)ptA * 3;
        const float pxA = ppA[0], pyA = ppA[1], pzA = ppA[2];
        const float* vA  = v  + (size_t)ptA * (K * 3);
        const float* vnA = vn + (size_t)ptA * (K * 3);
        const float* srA = sr + (size_t)ptA * K;
        const float* ppB = points + (size_t)ptB * 3;
        const float pxB = ppB[0], pyB = ppB[1], pzB = ppB[2];
        const float* vB  = v  + (size_t)ptB * (K * 3);
        const float* vnB = vn + (size_t)ptB * (K * 3);
        const float* srB = sr + (size_t)ptB * K;

        float numA = 0.0f, denA = 0.0f;
        float numB = 0.0f, denB = 0.0f;

        #pragma unroll
        for (int k = lane; k < K; k += 32) {
            const int b = k * 3;
            // 14 loads issued up front
            const float avx = vA[b + 0],  avy = vA[b + 1],  avz = vA[b + 2];
            const float anx = vnA[b + 0], any_ = vnA[b + 1], anz = vnA[b + 2];
            const float ra  = srA[k];
            const float bvx = vB[b + 0],  bvy = vB[b + 1],  bvz = vB[b + 2];
            const float bnx = vnB[b + 0], bny = vnB[b + 1], bnz = vnB[b + 2];
            const float rb  = srB[k];

            {
                const float dx = pxA - avx, dy = pyA - avy, dz = pzA - avz;
                const float d  = dx * dx + dy * dy + dz * dz;
                const float w  = 1.0f - __fdividef(d, ra);
                const float w2 = w * w;
                const float phi = (d < ra) ? (w2 * w2) : 1e-18f;
                const float dot = anx * dx + any_ * dy + anz * dz;
                numA = fmaf(phi, dot, numA);
                denA += phi;
            }
            {
                const float dx = pxB - bvx, dy = pyB - bvy, dz = pzB - bvz;
                const float d  = dx * dx + dy * dy + dz * dz;
                const float w  = 1.0f - __fdividef(d, rb);
                const float w2 = w * w;
                const float phi = (d < rb) ? (w2 * w2) : 1e-18f;
                const float dot = bnx * dx + bny * dy + bnz * dz;
                numB = fmaf(phi, dot, numB);
                denB += phi;
            }
        }

        #pragma unroll
        for (int off = 16; off > 0; off >>= 1) {
            numA += __shfl_xor_sync(0xffffffffu, numA, off);
            denA += __shfl_xor_sync(0xffffffffu, denA, off);
            numB += __shfl_xor_sync(0xffffffffu, numB, off);
            denB += __shfl_xor_sync(0xffffffffu, denB, off);
        }

        if (lane == 0) {
            const float sdfA = __fdividef(numA, denA);
            const float sdfB = __fdividef(numB, denB);
            float acc = sdfA * sdfA;
            if ((ptB / P) == (ptA / P)) {
                acc += sdfB * sdfB;
                atomicAdd(&s_acc[ptA / P], acc);
            } else {
                atomicAdd(&s_acc[ptA / P], acc);
                atomicAdd(&s_acc[ptB / P], sdfB * sdfB);
            }
        }
    }

    __syncthreads();

    // ---- finalize: scratch atomics + acq_rel ticket; last block writes out.
    // No __threadfence: atomics bypass L1 and are L2-coherent; the acq_rel
    // on the ticket provides the cross-block release/acquire ordering.
    if (tid == 0) {
        const float v0 = s_acc[0];
        const float v1 = s_acc[1];
        if (v0 != 0.0f) atomicAdd(&g_scratch[0], v0);
        if (v1 != 0.0f) atomicAdd(&g_scratch[1], v1);
        const unsigned t = ticket_inc_acq_rel();
        if (t == (unsigned)(nblocks - 1)) {
            out[0] = atomicExch(&g_scratch[0], 0.0f);
            out[1] = atomicExch(&g_scratch[1], 0.0f);
            atomicExch(&g_ticket, 0u);   // reset for next graph replay
        }
    }
}

// ---- generic fallback (any K / N / shape) ----
#define FB_WARPS 16
__global__ __launch_bounds__(FB_WARPS * 32)
void sdf_kernel_generic(const float* __restrict__ points,
                        const float* __restrict__ v,
                        const float* __restrict__ vn,
                        const float* __restrict__ sr,
                        float* __restrict__ out,
                        int total_pts, int P, int K)
{
    __shared__ float s_acc[2];
    const int tid  = threadIdx.x;
    if (tid < 2) s_acc[tid] = 0.0f;
    __syncthreads();

    const int warp = tid >> 5;
    const int lane = tid & 31;
    const int pt   = blockIdx.x * FB_WARPS + warp;

    if (pt < total_pts) {
        const float* pp = points + (size_t)pt * 3;
        const float px = pp[0], py = pp[1], pz = pp[2];
        const float* vb  = v  + (size_t)pt * K * 3;
        const float* vnb = vn + (size_t)pt * K * 3;
        const float* srb = sr + (size_t)pt * K;

        float num = 0.0f, den = 0.0f;
        for (int k = lane; k < K; k += 32) {
            const int b = k * 3;
            const float dx = px - vb[b + 0];
            const float dy = py - vb[b + 1];
            const float dz = pz - vb[b + 2];
            const float d  = dx * dx + dy * dy + dz * dz;
            const float r  = srb[k];
            const float w  = 1.0f - d / r;
            const float w2 = w * w;
            const float phi = (d < r) ? (w2 * w2) : 1e-18f;
            const float dot = vnb[b + 0] * dx + vnb[b + 1] * dy + vnb[b + 2] * dz;
            num = fmaf(phi, dot, num);
            den += phi;
        }
        #pragma unroll
        for (int off = 16; off > 0; off >>= 1) {
            num += __shfl_xor_sync(0xffffffffu, num, off);
            den += __shfl_xor_sync(0xffffffffu, den, off);
        }
        if (lane == 0) {
            const float sdf = num / den;
            atomicAdd(&s_acc[pt / P], sdf * sdf);
        }
    }
    __syncthreads();
    if (tid < 2) {
        const float val = s_acc[tid];
        if (val != 0.0f) atomicAdd(&out[tid], val);
    }
}

extern "C" void kernel_launch(void* const* d_in, const int* in_sizes, int n_in,
                              void* d_out, int out_size)
{
    const float* points = (const float*)d_in[0];
    const float* v      = (const float*)d_in[1];
    const float* vn     = (const float*)d_in[2];
    const float* sr     = (const float*)d_in[3];
    float* out          = (float*)d_out;

    const int total_pts = in_sizes[0] / 3;          // N*P
    const int N         = out_size;                 // 2
    const int P         = total_pts / N;            // 100000
    const int K         = in_sizes[3] / total_pts;  // 60

    if (K == 60 && N == 2 && (total_pts % 2) == 0) {
        const int pairs  = total_pts / 2;
        const int blocks = (pairs + WPB - 1) / WPB;
        sdf_fused60<<<blocks, TPB>>>(points, v, vn, sr, out,
                                     total_pts, P, blocks);
    } else {
        sdf_init_out<<<1, 32>>>(out, N);
        const int blocks = (total_pts + FB_WARPS - 1) / FB_WARPS;
        sdf_kernel_generic<<<blocks, FB_WARPS * 32>>>(points, v, vn, sr, out,
                                                      total_pts, P, K);
    }
}